// round 2
// baseline (speedup 1.0000x reference)
#include <cuda_runtime.h>
#include <cstddef>

// ---------------- problem constants ----------------
#define Dm   1024
#define Hh   16
#define HD   64
#define FFNm 4096
#define SEGm 128
#define LLm  256
#define MMm  4
#define BBm  64
#define UUm  128
#define RRm  32
#define TTm  160            // R + U
#define QQm  161            // R + U + 1 (summary)
#define KKm  420            // M + R + L + U
#define BD   (BBm*Dm)       // 65536
#define NEG_INF_F (-1e8f)
#define EPS_LN 1e-5f

// d_out section offsets (floats)
#define S0_OFF 0u                    // output_utterance 128*BD
#define S1_OFF 8388608u              // output_right_context 32*BD
#define S2_OFF 10485760u             // output_mems 1*BD
#define S3_OFF 10551296u             // new_mems 4*BD
#define S4_OFF 10813440u             // new_lc_key 256*BD
#define S5_OFF 27590656u             // new_lc_val 256*BD

// ---------------- scratch (static device globals; allocation-free) ----------------
__device__ float g_cat[165*BD];                 // [state_mems(4) | ln_rc(32) | ln_utt(128) | summary(1)]
__device__ float g_q[QQm*BD];
__device__ float g_k[KKm*BD];
__device__ float g_v[KKm*BD];
__device__ float g_scores[(size_t)1024*QQm*KKm];
__device__ float g_attn[QQm*BD];
__device__ float g_out[QQm*BD];
__device__ float g_res[TTm*BD];
__device__ float g_ffin[TTm*BD];
__device__ float g_ffh[(size_t)TTm*BBm*FFNm];
__device__ float g_ff2[TTm*BD];

// ---------------- reductions ----------------
__device__ __forceinline__ float block_sum_256(float v, float* sh) {
    int lane = threadIdx.x & 31, w = threadIdx.x >> 5;
#pragma unroll
    for (int o = 16; o; o >>= 1) v += __shfl_xor_sync(0xffffffffu, v, o);
    if (lane == 0) sh[w] = v;
    __syncthreads();
    if (w == 0) {
        float r = (lane < 8) ? sh[lane] : 0.0f;
#pragma unroll
        for (int o = 4; o; o >>= 1) r += __shfl_xor_sync(0xffffffffu, r, o);
        if (lane == 0) sh[0] = r;
    }
    __syncthreads();
    float out = sh[0];
    __syncthreads();
    return out;
}

// ---------------- LayerNorm kernels (one block per 1024-elem row, 256 thr) ----------------
__global__ void __launch_bounds__(256) k_ln_in(const float* __restrict__ rc,
                                               const float* __restrict__ utt,
                                               const float* __restrict__ gw,
                                               const float* __restrict__ bw) {
    __shared__ float sh[8];
    int row = blockIdx.x;  // 0..10239  (= t*64 + b over concat(rc, utt))
    const float* src = (row < RRm*BBm) ? rc + (size_t)row*Dm
                                       : utt + (size_t)(row - RRm*BBm)*Dm;
    float* dst = g_cat + (size_t)(4*BBm + row)*Dm;
    int tid = threadIdx.x;
    float4 x = ((const float4*)src)[tid];
    float mu = block_sum_256(x.x + x.y + x.z + x.w, sh) * (1.0f/Dm);
    float dx0 = x.x-mu, dx1 = x.y-mu, dx2 = x.z-mu, dx3 = x.w-mu;
    float var = block_sum_256(dx0*dx0 + dx1*dx1 + dx2*dx2 + dx3*dx3, sh) * (1.0f/Dm);
    float inv = rsqrtf(var + EPS_LN);
    float4 g4 = ((const float4*)gw)[tid], b4 = ((const float4*)bw)[tid];
    float4 o;
    o.x = dx0*inv*g4.x + b4.x; o.y = dx1*inv*g4.y + b4.y;
    o.z = dx2*inv*g4.z + b4.z; o.w = dx3*inv*g4.w + b4.w;
    ((float4*)dst)[tid] = o;
}

__global__ void __launch_bounds__(256) k_ln_ff(const float* __restrict__ gw,
                                               const float* __restrict__ bw) {
    __shared__ float sh[8];
    int row = blockIdx.x;  // 0..10239
    const float* src = g_res + (size_t)row*Dm;
    float* dst = g_ffin + (size_t)row*Dm;
    int tid = threadIdx.x;
    float4 x = ((const float4*)src)[tid];
    float mu = block_sum_256(x.x + x.y + x.z + x.w, sh) * (1.0f/Dm);
    float dx0 = x.x-mu, dx1 = x.y-mu, dx2 = x.z-mu, dx3 = x.w-mu;
    float var = block_sum_256(dx0*dx0 + dx1*dx1 + dx2*dx2 + dx3*dx3, sh) * (1.0f/Dm);
    float inv = rsqrtf(var + EPS_LN);
    float4 g4 = ((const float4*)gw)[tid], b4 = ((const float4*)bw)[tid];
    float4 o;
    o.x = dx0*inv*g4.x + b4.x; o.y = dx1*inv*g4.y + b4.y;
    o.z = dx2*inv*g4.z + b4.z; o.w = dx3*inv*g4.w + b4.w;
    ((float4*)dst)[tid] = o;
}

// final: LN(res + ff2) -> d_out sections 0/1 (rows t<32 -> right_context section)
__global__ void __launch_bounds__(256) k_ln_final(const float* __restrict__ gw,
                                                  const float* __restrict__ bw,
                                                  float* __restrict__ dout) {
    __shared__ float sh[8];
    int row = blockIdx.x;  // 0..10239
    int tid = threadIdx.x;
    float4 a = ((const float4*)(g_res + (size_t)row*Dm))[tid];
    float4 f = ((const float4*)(g_ff2 + (size_t)row*Dm))[tid];
    float4 x; x.x = a.x+f.x; x.y = a.y+f.y; x.z = a.z+f.z; x.w = a.w+f.w;
    float mu = block_sum_256(x.x + x.y + x.z + x.w, sh) * (1.0f/Dm);
    float dx0 = x.x-mu, dx1 = x.y-mu, dx2 = x.z-mu, dx3 = x.w-mu;
    float var = block_sum_256(dx0*dx0 + dx1*dx1 + dx2*dx2 + dx3*dx3, sh) * (1.0f/Dm);
    float inv = rsqrtf(var + EPS_LN);
    float4 g4 = ((const float4*)gw)[tid], b4 = ((const float4*)bw)[tid];
    float4 o;
    o.x = dx0*inv*g4.x + b4.x; o.y = dx1*inv*g4.y + b4.y;
    o.z = dx2*inv*g4.z + b4.z; o.w = dx3*inv*g4.w + b4.w;
    float* dst = (row < RRm*BBm) ? dout + S1_OFF + (size_t)row*Dm
                                 : dout + S0_OFF + (size_t)(row - RRm*BBm)*Dm;
    ((float4*)dst)[tid] = o;
}

// ---------------- summary = mean over utterance LN rows ----------------
__global__ void k_summary() {
    int e = blockIdx.x*blockDim.x + threadIdx.x;  // 0..65535 (b*D + d)
    float s = 0.0f;
#pragma unroll 8
    for (int t = 0; t < UUm; t++) s += g_cat[(size_t)(36 + t)*BD + e];
    g_cat[(size_t)164*BD + e] = s * (1.0f/SEGm);
}

// ---------------- generic GEMM NT:  C = alpha*(A @ W^T) + bias, optional relu ----
// A: M x K (row-major, lda), W: N x K (row-major, ldw). BM=128, BN=64, BK=16, 256 thr.
// K must be a multiple of 16, lda/ldw multiples of 4 (float4 loads).
__global__ void __launch_bounds__(256) gemm_nt(
    const float* __restrict__ A, int lda, long sAz,
    const float* __restrict__ W, int ldw, long sWz,
    const float* __restrict__ bias,
    float* __restrict__ C, int ldc, long sCz,
    int M, int N, int K, float alpha, int relu)
{
    __shared__ float As[16][132];
    __shared__ float Ws[16][68];
    A += (long)blockIdx.z * sAz; W += (long)blockIdx.z * sWz; C += (long)blockIdx.z * sCz;
    const int bm0 = blockIdx.y * 128, bn0 = blockIdx.x * 64;
    const int tid = threadIdx.x;
    const int tx = tid & 15, ty = tid >> 4;
    const int ar = tid >> 1, ak = (tid & 1) * 8;     // A loader: 128 rows x (2x float4)
    const int wr = tid >> 2, wk = (tid & 3) * 4;     // W loader: 64 rows x float4
    const bool avalid = (bm0 + ar) < M;
    const bool wvalid = (bn0 + wr) < N;
    const float* Aptr = A + (size_t)(bm0 + ar)*lda + ak;
    const float* Wptr = W + (size_t)(bn0 + wr)*ldw + wk;

    float acc[8][4];
#pragma unroll
    for (int i = 0; i < 8; i++)
#pragma unroll
        for (int j = 0; j < 4; j++) acc[i][j] = 0.0f;

    for (int k0 = 0; k0 < K; k0 += 16) {
        float4 a0 = make_float4(0,0,0,0), a1 = make_float4(0,0,0,0), w0 = make_float4(0,0,0,0);
        if (avalid) { a0 = *(const float4*)(Aptr + k0); a1 = *(const float4*)(Aptr + k0 + 4); }
        if (wvalid)   w0 = *(const float4*)(Wptr + k0);
        As[ak+0][ar]=a0.x; As[ak+1][ar]=a0.y; As[ak+2][ar]=a0.z; As[ak+3][ar]=a0.w;
        As[ak+4][ar]=a1.x; As[ak+5][ar]=a1.y; As[ak+6][ar]=a1.z; As[ak+7][ar]=a1.w;
        Ws[wk+0][wr]=w0.x; Ws[wk+1][wr]=w0.y; Ws[wk+2][wr]=w0.z; Ws[wk+3][wr]=w0.w;
        __syncthreads();
#pragma unroll
        for (int kk = 0; kk < 16; kk++) {
            float4 af0 = *(const float4*)&As[kk][ty*8];
            float4 af1 = *(const float4*)&As[kk][ty*8 + 4];
            float4 bf  = *(const float4*)&Ws[kk][tx*4];
            float av[8] = {af0.x,af0.y,af0.z,af0.w,af1.x,af1.y,af1.z,af1.w};
            float bv[4] = {bf.x,bf.y,bf.z,bf.w};
#pragma unroll
            for (int i = 0; i < 8; i++)
#pragma unroll
                for (int j = 0; j < 4; j++) acc[i][j] += av[i]*bv[j];
        }
        __syncthreads();
    }
#pragma unroll
    for (int i = 0; i < 8; i++) {
        int r = bm0 + ty*8 + i;
        if (r >= M) continue;
#pragma unroll
        for (int j = 0; j < 4; j++) {
            int c = bn0 + tx*4 + j;
            if (c >= N) continue;
            float v = acc[i][j] * alpha;
            if (bias) v += bias[c];
            if (relu) v = fmaxf(v, 0.0f);
            C[(size_t)r*ldc + c] = v;
        }
    }
}

// ---------------- generic GEMM NN: C = A @ B  (used for P @ V) --------------------
// A: M x K (lda), B: K x N (ldb). K may be non-multiple of 16 but multiple of 4.
__global__ void __launch_bounds__(256) gemm_nn(
    const float* __restrict__ A, int lda, long sAz,
    const float* __restrict__ Bm, int ldb, long sBz,
    float* __restrict__ C, int ldc, long sCz,
    int M, int N, int K)
{
    __shared__ float As[16][132];
    __shared__ float Bs[16][68];
    A += (long)blockIdx.z * sAz; Bm += (long)blockIdx.z * sBz; C += (long)blockIdx.z * sCz;
    const int bm0 = blockIdx.y * 128, bn0 = blockIdx.x * 64;
    const int tid = threadIdx.x;
    const int tx = tid & 15, ty = tid >> 4;
    const int ar = tid >> 1, ak = (tid & 1) * 8;
    const int br = tid >> 4, bc = (tid & 15) * 4;
    const bool avalid = (bm0 + ar) < M;
    const bool bnvalid = (bn0 + bc) < N;
    const float* Aptr = A + (size_t)(bm0 + ar)*lda + ak;

    float acc[8][4];
#pragma unroll
    for (int i = 0; i < 8; i++)
#pragma unroll
        for (int j = 0; j < 4; j++) acc[i][j] = 0.0f;

    for (int k0 = 0; k0 < K; k0 += 16) {
        float4 a0 = make_float4(0,0,0,0), a1 = make_float4(0,0,0,0), b0 = make_float4(0,0,0,0);
        if (avalid) {
            if (k0 + ak     < K) a0 = *(const float4*)(Aptr + k0);
            if (k0 + ak + 4 < K) a1 = *(const float4*)(Aptr + k0 + 4);
        }
        if ((k0 + br) < K && bnvalid)
            b0 = *(const float4*)(Bm + (size_t)(k0 + br)*ldb + bn0 + bc);
        As[ak+0][ar]=a0.x; As[ak+1][ar]=a0.y; As[ak+2][ar]=a0.z; As[ak+3][ar]=a0.w;
        As[ak+4][ar]=a1.x; As[ak+5][ar]=a1.y; As[ak+6][ar]=a1.z; As[ak+7][ar]=a1.w;
        Bs[br][bc+0]=b0.x; Bs[br][bc+1]=b0.y; Bs[br][bc+2]=b0.z; Bs[br][bc+3]=b0.w;
        __syncthreads();
#pragma unroll
        for (int kk = 0; kk < 16; kk++) {
            float4 af0 = *(const float4*)&As[kk][ty*8];
            float4 af1 = *(const float4*)&As[kk][ty*8 + 4];
            float4 bf  = *(const float4*)&Bs[kk][tx*4];
            float av[8] = {af0.x,af0.y,af0.z,af0.w,af1.x,af1.y,af1.z,af1.w};
            float bv[4] = {bf.x,bf.y,bf.z,bf.w};
#pragma unroll
            for (int i = 0; i < 8; i++)
#pragma unroll
                for (int j = 0; j < 4; j++) acc[i][j] += av[i]*bv[j];
        }
        __syncthreads();
    }
#pragma unroll
    for (int i = 0; i < 8; i++) {
        int r = bm0 + ty*8 + i;
        if (r >= M) continue;
#pragma unroll
        for (int j = 0; j < 4; j++) {
            int c = bn0 + tx*4 + j;
            if (c >= N) continue;
            C[(size_t)r*ldc + c] = acc[i][j];
        }
    }
}

// ---------------- masked softmax over K=420, one block per (bh, q) row ------------
__global__ void __launch_bounds__(128) k_softmax(const int* __restrict__ past_len) {
    __shared__ float sred[4];
    int idx = blockIdx.x;
    int q  = idx % QQm;
    int bh = idx / QQm;
    float* row = g_scores + (size_t)bh*(QQm*KKm) + (size_t)q*KKm;
    int pl   = past_len[0];
    int m_kv = min(LLm, pl);
    int m_m  = min(MMm, pl / SEGm);
    int tid = threadIdx.x, lane = tid & 31, w = tid >> 5;

    float v[4];
    float mx = -3.4e38f;
#pragma unroll
    for (int j = 0; j < 4; j++) {
        int c = tid + 128*j;
        float val = -3.4e38f;
        if (c < KKm) {
            bool msk = (c < MMm - m_m) ||
                       (c >= MMm + RRm && c < MMm + RRm + (LLm - m_kv)) ||
                       (q == QQm - 1 && c < MMm);
            val = msk ? NEG_INF_F : row[c];
        }
        v[j] = val;
        mx = fmaxf(mx, val);
    }
#pragma unroll
    for (int o = 16; o; o >>= 1) mx = fmaxf(mx, __shfl_xor_sync(0xffffffffu, mx, o));
    if (lane == 0) sred[w] = mx;
    __syncthreads();
    mx = fmaxf(fmaxf(sred[0], sred[1]), fmaxf(sred[2], sred[3]));
    __syncthreads();

    float s = 0.0f;
#pragma unroll
    for (int j = 0; j < 4; j++) {
        int c = tid + 128*j;
        if (c < KKm) { v[j] = expf(v[j] - mx); s += v[j]; }
    }
#pragma unroll
    for (int o = 16; o; o >>= 1) s += __shfl_xor_sync(0xffffffffu, s, o);
    if (lane == 0) sred[w] = s;
    __syncthreads();
    s = sred[0] + sred[1] + sred[2] + sred[3];
    float r = 1.0f / s;
#pragma unroll
    for (int j = 0; j < 4; j++) {
        int c = tid + 128*j;
        if (c < KKm) row[c] = v[j] * r;
    }
}

// ---------------- residual add, clip ----------------
__global__ void k_resadd(const float* __restrict__ rc, const float* __restrict__ utt) {
    size_t i = (size_t)blockIdx.x*blockDim.x + threadIdx.x;     // float4 index, n4 = 160*BD/4
    float4 o = ((const float4*)g_out)[i];
    size_t rc4 = (size_t)RRm*BD/4;
    float4 s = (i < rc4) ? ((const float4*)rc)[i] : ((const float4*)utt)[i - rc4];
    float4 r; r.x = o.x+s.x; r.y = o.y+s.y; r.z = o.z+s.z; r.w = o.w+s.w;
    ((float4*)g_res)[i] = r;
}

__global__ void k_clip(float* __restrict__ dout) {
    size_t i = (size_t)blockIdx.x*blockDim.x + threadIdx.x;     // float4 index over BD/4
    float4 v = ((const float4*)(g_out + (size_t)TTm*BD))[i];
    v.x = fminf(fmaxf(v.x, -10.f), 10.f);
    v.y = fminf(fmaxf(v.y, -10.f), 10.f);
    v.z = fminf(fmaxf(v.z, -10.f), 10.f);
    v.w = fminf(fmaxf(v.w, -10.f), 10.f);
    ((float4*)(dout + S2_OFF))[i] = v;
}

// ---------------- launcher ----------------
extern "C" void kernel_launch(void* const* d_in, const int* in_sizes, int n_in,
                              void* d_out_v, int out_size) {
    const float* utterance   = (const float*)d_in[0];
    const float* right_ctx   = (const float*)d_in[1];
    const float* mems_in     = (const float*)d_in[2];
    const float* state_mems  = (const float*)d_in[3];
    const float* lc_key      = (const float*)d_in[4];
    const float* lc_val      = (const float*)d_in[5];
    const float* W_kv        = (const float*)d_in[6];
    const float* b_kv        = (const float*)d_in[7];
    const float* W_q         = (const float*)d_in[8];
    const float* b_q         = (const float*)d_in[9];
    const float* W_out       = (const float*)d_in[10];
    const float* b_out       = (const float*)d_in[11];
    const float* ln_in_g     = (const float*)d_in[12];
    const float* ln_in_b     = (const float*)d_in[13];
    const float* ln_ff_g     = (const float*)d_in[14];
    const float* ln_ff_b     = (const float*)d_in[15];
    const float* W_ff1       = (const float*)d_in[16];
    const float* b_ff1       = (const float*)d_in[17];
    const float* W_ff2       = (const float*)d_in[18];
    const float* b_ff2       = (const float*)d_in[19];
    const float* ln_out_g    = (const float*)d_in[20];
    const float* ln_out_b    = (const float*)d_in[21];
    const int*   past_len    = (const int*)  d_in[22];
    float* dout = (float*)d_out_v;

    float *cat, *q, *k, *v, *scores, *attn, *outb, *ffin, *ffh, *ff2b;
    cudaGetSymbolAddress((void**)&cat,    g_cat);
    cudaGetSymbolAddress((void**)&q,      g_q);
    cudaGetSymbolAddress((void**)&k,      g_k);
    cudaGetSymbolAddress((void**)&v,      g_v);
    cudaGetSymbolAddress((void**)&scores, g_scores);
    cudaGetSymbolAddress((void**)&attn,   g_attn);
    cudaGetSymbolAddress((void**)&outb,   g_out);
    cudaGetSymbolAddress((void**)&ffin,   g_ffin);
    cudaGetSymbolAddress((void**)&ffh,    g_ffh);
    cudaGetSymbolAddress((void**)&ff2b,   g_ff2);

    // 1. state_mems -> g_cat rows 0..3
    cudaMemcpyAsync(cat, state_mems, (size_t)4*BD*sizeof(float),
                    cudaMemcpyDeviceToDevice, 0);
    // 2. LN over concat(rc, utt) -> g_cat rows 4..163
    k_ln_in<<<TTm*BBm, 256>>>(right_ctx, utterance, ln_in_g, ln_in_b);
    // 3. summary -> g_cat row 164
    k_summary<<<BD/256, 256>>>();

    // 4. query = q_in @ W_q^T + b_q      (q_in = g_cat rows 4..164, M = 161*64)
    gemm_nt<<<dim3(16, 81, 1), 256>>>(cat + (size_t)4*BD, Dm, 0, W_q, Dm, 0, b_q,
                                      q, Dm, 0, QQm*BBm, Dm, Dm, 1.0f, 0);
    // 5-8. k_all / v_all split directly into g_k/g_v (rows 0..35 and 292..419)
    gemm_nt<<<dim3(16, 18, 1), 256>>>(cat, Dm, 0, W_kv, Dm, 0, b_kv,
                                      k, Dm, 0, 36*BBm, Dm, Dm, 1.0f, 0);
    gemm_nt<<<dim3(16, 64, 1), 256>>>(cat + (size_t)36*BD, Dm, 0, W_kv, Dm, 0, b_kv,
                                      k + (size_t)292*BD, Dm, 0, UUm*BBm, Dm, Dm, 1.0f, 0);
    gemm_nt<<<dim3(16, 18, 1), 256>>>(cat, Dm, 0, W_kv + (size_t)Dm*Dm, Dm, 0, b_kv + Dm,
                                      v, Dm, 0, 36*BBm, Dm, Dm, 1.0f, 0);
    gemm_nt<<<dim3(16, 64, 1), 256>>>(cat + (size_t)36*BD, Dm, 0, W_kv + (size_t)Dm*Dm, Dm, 0, b_kv + Dm,
                                      v + (size_t)292*BD, Dm, 0, UUm*BBm, Dm, Dm, 1.0f, 0);
    // 9-10. cached local-context K/V into the middle
    cudaMemcpyAsync(k + (size_t)36*BD, lc_key, (size_t)LLm*BD*sizeof(float),
                    cudaMemcpyDeviceToDevice, 0);
    cudaMemcpyAsync(v + (size_t)36*BD, lc_val, (size_t)LLm*BD*sizeof(float),
                    cudaMemcpyDeviceToDevice, 0);

    // 11. scores = 0.125 * Qh @ Kh^T   (batched over bh=1024)
    gemm_nt<<<dim3(7, 2, 1024), 256>>>(q, BD, 64, k, BD, 64, nullptr,
                                       scores, KKm, (long)QQm*KKm,
                                       QQm, KKm, HD, 0.125f, 0);
    // 12. masked softmax
    k_softmax<<<1024*QQm, 128>>>(past_len);
    // 13. attn = P @ Vh  (batched)
    gemm_nn<<<dim3(1, 2, 1024), 256>>>(scores, KKm, (long)QQm*KKm, v, BD, 64,
                                       attn, BD, 64, QQm, HD, KKm);
    // 14. out = attn @ W_out^T + b_out
    gemm_nt<<<dim3(16, 81, 1), 256>>>(attn, Dm, 0, W_out, Dm, 0, b_out,
                                      outb, Dm, 0, QQm*BBm, Dm, Dm, 1.0f, 0);
    // 15. residual, 16. clipped mems output
    k_resadd<<<(TTm*BD/4)/256, 256>>>(right_ctx, utterance);
    k_clip<<<(BD/4)/256, 256>>>(dout);
    // 17. LN for FFN
    k_ln_ff<<<TTm*BBm, 256>>>(ln_ff_g, ln_ff_b);
    // 18-19. FFN
    gemm_nt<<<dim3(64, 80, 1), 256>>>(ffin, Dm, 0, W_ff1, Dm, 0, b_ff1,
                                      ffh, FFNm, 0, TTm*BBm, FFNm, Dm, 1.0f, 1);
    gemm_nt<<<dim3(16, 80, 1), 256>>>(ffh, FFNm, 0, W_ff2, FFNm, 0, b_ff2,
                                      ff2b, Dm, 0, TTm*BBm, Dm, FFNm, 1.0f, 0);
    // 20. final LN -> output_utterance / output_right_context
    k_ln_final<<<TTm*BBm, 256>>>(ln_out_g, ln_out_b, dout);

    // 21+. state-carry outputs
    cudaMemcpyAsync(dout + S3_OFF, state_mems + BD, (size_t)3*BD*sizeof(float),
                    cudaMemcpyDeviceToDevice, 0);
    cudaMemcpyAsync(dout + S3_OFF + (size_t)3*BD, mems_in, (size_t)BD*sizeof(float),
                    cudaMemcpyDeviceToDevice, 0);
    cudaMemcpyAsync(dout + S4_OFF, lc_key + (size_t)128*BD, (size_t)128*BD*sizeof(float),
                    cudaMemcpyDeviceToDevice, 0);
    cudaMemcpyAsync(dout + S4_OFF + (size_t)128*BD, k + (size_t)292*BD,
                    (size_t)128*BD*sizeof(float), cudaMemcpyDeviceToDevice, 0);
    cudaMemcpyAsync(dout + S5_OFF, lc_val + (size_t)128*BD, (size_t)128*BD*sizeof(float),
                    cudaMemcpyDeviceToDevice, 0);
    cudaMemcpyAsync(dout + S5_OFF + (size_t)128*BD, v + (size_t)292*BD,
                    (size_t)128*BD*sizeof(float), cudaMemcpyDeviceToDevice, 0);
}

// round 4
// speedup vs baseline: 2.9912x; 2.9912x over previous
#include <cuda_runtime.h>
#include <cuda_bf16.h>
#include <cstdint>
#include <cstddef>

#define Dm 1024
#define FFNm 4096
#define SEGm 128
#define LLm 256
#define MMm 4
#define BBm 64
#define UUm 128
#define RRm 32
#define TTm 160
#define QQm 161
#define KKm 420
#define BD (BBm*Dm)
#define NEG_INF_F (-1e8f)
#define EPS_LN 1e-5f
#define S0_OFF 0u
#define S1_OFF 8388608u
#define S2_OFF 10485760u
#define S3_OFF 10551296u
#define S4_OFF 10813440u
#define S5_OFF 27590656u

typedef __nv_bfloat16 bf16;
typedef __nv_bfloat162 bf162;

__device__ float g_cat[165*BD];
__device__ float g_q[QQm*BD];
__device__ float g_k[KKm*BD];
__device__ float g_v[KKm*BD];
__device__ float g_scores[(size_t)1024*QQm*KKm];
__device__ float g_attn[QQm*BD];
__device__ float g_out[QQm*BD];
__device__ float g_res[TTm*BD];
__device__ float g_ff2[TTm*BD];
__device__ bf16 g_cat_h[165*BD], g_cat_l[165*BD];
__device__ bf16 g_ffin_h[TTm*BD], g_ffin_l[TTm*BD];
__device__ bf16 g_ffh_h[(size_t)TTm*BBm*FFNm], g_ffh_l[(size_t)TTm*BBm*FFNm];
__device__ bf16 g_attn_h[QQm*BD], g_attn_l[QQm*BD];
__device__ bf16 g_wq_h[Dm*Dm], g_wq_l[Dm*Dm];
__device__ bf16 g_wkv_h[2*Dm*Dm], g_wkv_l[2*Dm*Dm];
__device__ bf16 g_wo_h[Dm*Dm], g_wo_l[Dm*Dm];
__device__ bf16 g_w1_h[FFNm*Dm], g_w1_l[FFNm*Dm];
__device__ bf16 g_w2_h[Dm*FFNm], g_w2_l[Dm*FFNm];

__device__ __forceinline__ uint32_t smem_u32(const void* p){
    uint32_t a; asm("{ .reg .u64 t; cvta.to.shared.u64 t, %1; cvt.u32.u64 %0, t; }":"=r"(a):"l"(p)); return a;
}
__device__ __forceinline__ void cp16(uint32_t dst, const void* src){
    asm volatile("cp.async.cg.shared.global [%0], [%1], 16;"::"r"(dst),"l"(src));
}
__device__ __forceinline__ void ldsm4(uint32_t* r, uint32_t addr){
    asm volatile("ldmatrix.sync.aligned.m8n8.x4.shared.b16 {%0,%1,%2,%3}, [%4];"
        :"=r"(r[0]),"=r"(r[1]),"=r"(r[2]),"=r"(r[3]):"r"(addr));
}
__device__ __forceinline__ void mma16816(float* c, const uint32_t* a, uint32_t b0, uint32_t b1){
    asm volatile("mma.sync.aligned.m16n8k16.row.col.f32.bf16.bf16.f32 "
        "{%0,%1,%2,%3}, {%4,%5,%6,%7}, {%8,%9}, {%0,%1,%2,%3};"
        :"+f"(c[0]),"+f"(c[1]),"+f"(c[2]),"+f"(c[3])
        :"r"(a[0]),"r"(a[1]),"r"(a[2]),"r"(a[3]),"r"(b0),"r"(b1));
}

// ---- HMMA split-bf16 GEMM: out = A@B^T (+bias)(relu). Tile 128x128, BK=32 ----
// smem: 2 bufs x (A 128x40bf16 + B 128x40bf16) = 40960 B
#define ROWB 80
__global__ void __launch_bounds__(256,2) gemm_mma(
    const bf16* __restrict__ Ahi, const bf16* __restrict__ Alo, int lda,
    const bf16* __restrict__ Bhi, const bf16* __restrict__ Blo, int ldb,
    const float* __restrict__ bias, float* __restrict__ C,
    bf16* __restrict__ Chi, bf16* __restrict__ Clo, int ldc, int M, int K, int relu)
{
    __shared__ __align__(16) char smbuf[2*2*10240];
    const int tid = threadIdx.x, wid = tid>>5, lane = tid&31;
    const int m0 = blockIdx.y*128, n0 = blockIdx.x*128;
    const int m0w = (wid>>1)*32, n0w = (wid&1)*64;
    const uint32_t sb = smem_u32(smbuf);
    const int kch = K>>5;           // 32-wide chunks per pass
    const int nIt = 3*kch;

    float acc[2][8][4];
#pragma unroll
    for(int i=0;i<2;i++)
#pragma unroll
        for(int j=0;j<8;j++)
#pragma unroll
            for(int l=0;l<4;l++) acc[i][j][l]=0.f;

    // loader: per-thread 2 A-chunks + 2 B-chunks of 16B
    const int lrow = tid>>2, lch = tid&3;       // 64 rows per 256-thread pass
    auto load_tile = [&](int it, int buf){
        int phase = it/kch, kk = (it - phase*kch)<<5;
        const bf16* Ap = (phase==2)? Alo : Ahi;
        const bf16* Bp = (phase==1)? Blo : Bhi;
        uint32_t aB = sb + buf*20480, bB = aB + 10240;
#pragma unroll
        for(int h=0; h<2; ++h){
            int row = lrow + h*64;
            int gr = m0+row; if (gr >= M) gr = M-1;
            cp16(aB + row*ROWB + lch*16, Ap + (size_t)gr*lda + kk + lch*8);
            cp16(bB + row*ROWB + lch*16, Bp + (size_t)(n0+row)*ldb + kk + lch*8);
        }
        asm volatile("cp.async.commit_group;":::"memory");
    };

    load_tile(0, 0);
    for(int it=0; it<nIt; ++it){
        int buf = it&1;
        if (it+1 < nIt){
            load_tile(it+1, buf^1);
            asm volatile("cp.async.wait_group 1;":::"memory");
        } else {
            asm volatile("cp.async.wait_group 0;":::"memory");
        }
        __syncthreads();
        uint32_t aB = sb + buf*20480, bB = aB + 10240;
        // per-lane ldmatrix row offsets
        uint32_t aoff = aB + (uint32_t)(m0w + (lane&15))*ROWB + ((lane>>4)<<4);
        uint32_t boff = bB + (uint32_t)(n0w + (lane&7) + ((lane>>4)<<3))*ROWB + (((lane>>3)&1)<<4);
#pragma unroll
        for(int ks=0; ks<2; ++ks){
            uint32_t a[2][4], b[4][4];
            ldsm4(a[0], aoff + ks*32);
            ldsm4(a[1], aoff + 16*ROWB + ks*32);
#pragma unroll
            for(int np=0; np<4; ++np)
                ldsm4(b[np], boff + np*16*ROWB + ks*32);
#pragma unroll
            for(int mt=0; mt<2; ++mt)
#pragma unroll
                for(int nt=0; nt<8; ++nt){
                    int p = nt>>1, h = (nt&1)<<1;
                    mma16816(acc[mt][nt], a[mt], b[p][h], b[p][h+1]);
                }
        }
        __syncthreads();
    }

    // epilogue
#pragma unroll
    for(int mt=0; mt<2; ++mt){
        int r0 = m0 + m0w + mt*16 + (lane>>2);
#pragma unroll
        for(int nt=0; nt<8; ++nt){
            int c = n0 + n0w + nt*8 + ((lane&3)<<1);
            float b0 = bias ? __ldg(bias+c) : 0.f;
            float b1 = bias ? __ldg(bias+c+1) : 0.f;
#pragma unroll
            for(int hrow=0; hrow<2; ++hrow){
                int r = r0 + hrow*8;
                if (r >= M) continue;
                float v0 = acc[mt][nt][hrow*2]   + b0;
                float v1 = acc[mt][nt][hrow*2+1] + b1;
                if (relu){ v0=fmaxf(v0,0.f); v1=fmaxf(v1,0.f); }
                if (C) *(float2*)(C + (size_t)r*ldc + c) = make_float2(v0,v1);
                if (Chi){
                    bf16 h0=__float2bfloat16(v0), h1=__float2bfloat16(v1);
                    bf16 l0=__float2bfloat16(v0-__bfloat162float(h0));
                    bf16 l1=__float2bfloat16(v1-__bfloat162float(h1));
                    *(uint32_t*)(Chi+(size_t)r*ldc+c) = (uint32_t)__bfloat16_as_ushort(h0)|((uint32_t)__bfloat16_as_ushort(h1)<<16);
                    *(uint32_t*)(Clo+(size_t)r*ldc+c) = (uint32_t)__bfloat16_as_ushort(l0)|((uint32_t)__bfloat16_as_ushort(l1)<<16);
                }
            }
        }
    }
}

// ---- fp32 -> (hi,lo) bf16 split ----
__device__ __forceinline__ void split4(float4 v, bf162* hp, bf162* lp, size_t i2){
    bf16 h0=__float2bfloat16(v.x), h1=__float2bfloat16(v.y);
    bf16 h2=__float2bfloat16(v.z), h3=__float2bfloat16(v.w);
    hp[i2]=__halves2bfloat162(h0,h1); hp[i2+1]=__halves2bfloat162(h2,h3);
    lp[i2]=__halves2bfloat162(__float2bfloat16(v.x-__bfloat162float(h0)),__float2bfloat16(v.y-__bfloat162float(h1)));
    lp[i2+1]=__halves2bfloat162(__float2bfloat16(v.z-__bfloat162float(h2)),__float2bfloat16(v.w-__bfloat162float(h3)));
}
__global__ void k_split(const float* __restrict__ s, bf16* __restrict__ h, bf16* __restrict__ l){
    size_t i=(size_t)blockIdx.x*blockDim.x+threadIdx.x;
    split4(((const float4*)s)[i], (bf162*)h, (bf162*)l, 2*i);
}

__device__ __forceinline__ float bsum(float v, float* sh){
    int lane=threadIdx.x&31, w=threadIdx.x>>5;
#pragma unroll
    for(int o=16;o;o>>=1) v+=__shfl_xor_sync(0xffffffffu,v,o);
    if(lane==0) sh[w]=v;
    __syncthreads();
    if(w==0){ float r=(lane<8)?sh[lane]:0.f;
#pragma unroll
        for(int o=4;o;o>>=1) r+=__shfl_xor_sync(0xffffffffu,r,o);
        if(lane==0) sh[0]=r; }
    __syncthreads(); float o=sh[0]; __syncthreads(); return o;
}
__device__ __forceinline__ float4 ln_core(float4 x, const float* gw, const float* bw, int tid, float* sh){
    float mu=bsum(x.x+x.y+x.z+x.w,sh)*(1.f/Dm);
    float d0=x.x-mu,d1=x.y-mu,d2=x.z-mu,d3=x.w-mu;
    float var=bsum(d0*d0+d1*d1+d2*d2+d3*d3,sh)*(1.f/Dm);
    float inv=rsqrtf(var+EPS_LN);
    float4 g4=((const float4*)gw)[tid], b4=((const float4*)bw)[tid];
    return make_float4(d0*inv*g4.x+b4.x, d1*inv*g4.y+b4.y, d2*inv*g4.z+b4.z, d3*inv*g4.w+b4.w);
}
__global__ void __launch_bounds__(256) k_ln_in(const float* __restrict__ rc, const float* __restrict__ utt,
                                               const float* __restrict__ gw, const float* __restrict__ bw){
    __shared__ float sh[8];
    int row=blockIdx.x, tid=threadIdx.x;
    const float* src=(row<RRm*BBm)?rc+(size_t)row*Dm:utt+(size_t)(row-RRm*BBm)*Dm;
    float4 o=ln_core(((const float4*)src)[tid],gw,bw,tid,sh);
    size_t base=(size_t)(4*BBm+row)*Dm;
    ((float4*)(g_cat+base))[tid]=o;
    split4(o,(bf162*)(g_cat_h+base),(bf162*)(g_cat_l+base),2*(size_t)tid);
}
__global__ void __launch_bounds__(256) k_ln_ff(const float* __restrict__ gw, const float* __restrict__ bw){
    __shared__ float sh[8];
    int row=blockIdx.x, tid=threadIdx.x;
    size_t base=(size_t)row*Dm;
    float4 o=ln_core(((const float4*)(g_res+base))[tid],gw,bw,tid,sh);
    split4(o,(bf162*)(g_ffin_h+base),(bf162*)(g_ffin_l+base),2*(size_t)tid);
}
__global__ void __launch_bounds__(256) k_ln_final(const float* __restrict__ gw, const float* __restrict__ bw,
                                                  float* __restrict__ dout){
    __shared__ float sh[8];
    int row=blockIdx.x, tid=threadIdx.x;
    float4 a=((const float4*)(g_res+(size_t)row*Dm))[tid];
    float4 f=((const float4*)(g_ff2+(size_t)row*Dm))[tid];
    float4 o=ln_core(make_float4(a.x+f.x,a.y+f.y,a.z+f.z,a.w+f.w),gw,bw,tid,sh);
    float* dst=(row<RRm*BBm)?dout+S1_OFF+(size_t)row*Dm:dout+S0_OFF+(size_t)(row-RRm*BBm)*Dm;
    ((float4*)dst)[tid]=o;
}
__global__ void k_summary(){
    int e=blockIdx.x*blockDim.x+threadIdx.x;
    float s=0.f;
#pragma unroll 8
    for(int t=0;t<UUm;t++) s+=g_cat[(size_t)(36+t)*BD+e];
    float v=s*(1.f/SEGm);
    size_t o=(size_t)164*BD+e;
    bf16 h=__float2bfloat16(v);
    g_cat_h[o]=h; g_cat_l[o]=__float2bfloat16(v-__bfloat162float(h));
}

// ---- SIMT NT gemm (scores) ----
__global__ void __launch_bounds__(256) gemm_nt(
    const float* __restrict__ A, int lda, long sAz,
    const float* __restrict__ W, int ldw, long sWz,
    float* __restrict__ C, int ldc, long sCz, int M, int N, int K, float alpha)
{
    __shared__ float As[16][132];
    __shared__ float Ws[16][68];
    A+=(long)blockIdx.z*sAz; W+=(long)blockIdx.z*sWz; C+=(long)blockIdx.z*sCz;
    const int bm0=blockIdx.y*128, bn0=blockIdx.x*64;
    const int tid=threadIdx.x, tx=tid&15, ty=tid>>4;
    const int ar=tid>>1, ak=(tid&1)*8, wr=tid>>2, wk=(tid&3)*4;
    const bool av=(bm0+ar)<M, wv=(bn0+wr)<N;
    const float* Ap=A+(size_t)(bm0+ar)*lda+ak;
    const float* Wp=W+(size_t)(bn0+wr)*ldw+wk;
    float acc[8][4];
#pragma unroll
    for(int i=0;i<8;i++)
#pragma unroll
        for(int j=0;j<4;j++) acc[i][j]=0.f;
    for(int k0=0;k0<K;k0+=16){
        float4 a0=make_float4(0,0,0,0),a1=a0,w0=a0;
        if(av){a0=*(const float4*)(Ap+k0); a1=*(const float4*)(Ap+k0+4);}
        if(wv) w0=*(const float4*)(Wp+k0);
        As[ak+0][ar]=a0.x;As[ak+1][ar]=a0.y;As[ak+2][ar]=a0.z;As[ak+3][ar]=a0.w;
        As[ak+4][ar]=a1.x;As[ak+5][ar]=a1.y;As[ak+6][ar]=a1.z;As[ak+7][ar]=a1.w;
        Ws[wk+0][wr]=w0.x;Ws[wk+1][wr]=w0.y;Ws[wk+2][wr]=w0.z;Ws[wk+3][wr]=w0.w;
        __syncthreads();
#pragma unroll
        for(int kk=0;kk<16;kk++){
            float4 f0=*(const float4*)&As[kk][ty*8], f1=*(const float4*)&As[kk][ty*8+4];
            float4 bf=*(const float4*)&Ws[kk][tx*4];
            float avv[8]={f0.x,f0.y,f0.z,f0.w,f1.x,f1.y,f1.z,f1.w};
            float bv[4]={bf.x,bf.y,bf.z,bf.w};
#pragma unroll
            for(int i=0;i<8;i++)
#pragma unroll
                for(int j=0;j<4;j++) acc[i][j]+=avv[i]*bv[j];
        }
        __syncthreads();
    }
#pragma unroll
    for(int i=0;i<8;i++){
        int r=bm0+ty*8+i; if(r>=M) continue;
#pragma unroll
        for(int j=0;j<4;j++){
            int c=bn0+tx*4+j; if(c>=N) continue;
            C[(size_t)r*ldc+c]=acc[i][j]*alpha;
        }
    }
}
// ---- SIMT NN gemm (P@V) ----
__global__ void __launch_bounds__(256) gemm_nn(
    const float* __restrict__ A, int lda, long sAz,
    const float* __restrict__ Bm, int ldb, long sBz,
    float* __restrict__ C, int ldc, long sCz, int M, int N, int K)
{
    __shared__ float As[16][132];
    __shared__ float Bs[16][68];
    A+=(long)blockIdx.z*sAz; Bm+=(long)blockIdx.z*sBz; C+=(long)blockIdx.z*sCz;
    const int bm0=blockIdx.y*128, bn0=blockIdx.x*64;
    const int tid=threadIdx.x, tx=tid&15, ty=tid>>4;
    const int ar=tid>>1, ak=(tid&1)*8, br=tid>>4, bc=(tid&15)*4;
    const bool av=(bm0+ar)<M, bnv=(bn0+bc)<N;
    const float* Ap=A+(size_t)(bm0+ar)*lda+ak;
    float acc[8][4];
#pragma unroll
    for(int i=0;i<8;i++)
#pragma unroll
        for(int j=0;j<4;j++) acc[i][j]=0.f;
    for(int k0=0;k0<K;k0+=16){
        float4 a0=make_float4(0,0,0,0),a1=a0,b0=a0;
        if(av){ if(k0+ak<K) a0=*(const float4*)(Ap+k0); if(k0+ak+4<K) a1=*(const float4*)(Ap+k0+4); }
        if((k0+br)<K && bnv) b0=*(const float4*)(Bm+(size_t)(k0+br)*ldb+bn0+bc);
        As[ak+0][ar]=a0.x;As[ak+1][ar]=a0.y;As[ak+2][ar]=a0.z;As[ak+3][ar]=a0.w;
        As[ak+4][ar]=a1.x;As[ak+5][ar]=a1.y;As[ak+6][ar]=a1.z;As[ak+7][ar]=a1.w;
        Bs[br][bc+0]=b0.x;Bs[br][bc+1]=b0.y;Bs[br][bc+2]=b0.z;Bs[br][bc+3]=b0.w;
        __syncthreads();
#pragma unroll
        for(int kk=0;kk<16;kk++){
            float4 f0=*(const float4*)&As[kk][ty*8], f1=*(const float4*)&As[kk][ty*8+4];
            float4 bf=*(const float4*)&Bs[kk][tx*4];
            float avv[8]={f0.x,f0.y,f0.z,f0.w,f1.x,f1.y,f1.z,f1.w};
            float bv[4]={bf.x,bf.y,bf.z,bf.w};
#pragma unroll
            for(int i=0;i<8;i++)
#pragma unroll
                for(int j=0;j<4;j++) acc[i][j]+=avv[i]*bv[j];
        }
        __syncthreads();
    }
#pragma unroll
    for(int i=0;i<8;i++){
        int r=bm0+ty*8+i; if(r>=M) continue;
#pragma unroll
        for(int j=0;j<4;j++){
            int c=bn0+tx*4+j; if(c>=N) continue;
            C[(size_t)r*ldc+c]=acc[i][j];
        }
    }
}

__global__ void __launch_bounds__(128) k_softmax(const int* __restrict__ past_len){
    __shared__ float sred[4];
    int idx=blockIdx.x, q=idx%QQm, bh=idx/QQm;
    float* row=g_scores+(size_t)bh*(QQm*KKm)+(size_t)q*KKm;
    int pl=past_len[0], m_kv=min(LLm,pl), m_m=min(MMm,pl/SEGm);
    int tid=threadIdx.x, lane=tid&31, w=tid>>5;
    float v[4], mx=-3.4e38f;
#pragma unroll
    for(int j=0;j<4;j++){
        int c=tid+128*j; float val=-3.4e38f;
        if(c<KKm){
            bool msk=(c<MMm-m_m)||(c>=MMm+RRm && c<MMm+RRm+(LLm-m_kv))||(q==QQm-1 && c<MMm);
            val=msk?NEG_INF_F:row[c];
        }
        v[j]=val; mx=fmaxf(mx,val);
    }
#pragma unroll
    for(int o=16;o;o>>=1) mx=fmaxf(mx,__shfl_xor_sync(0xffffffffu,mx,o));
    if(lane==0) sred[w]=mx;
    __syncthreads();
    mx=fmaxf(fmaxf(sred[0],sred[1]),fmaxf(sred[2],sred[3]));
    __syncthreads();
    float s=0.f;
#pragma unroll
    for(int j=0;j<4;j++){ int c=tid+128*j; if(c<KKm){ v[j]=expf(v[j]-mx); s+=v[j]; } }
#pragma unroll
    for(int o=16;o;o>>=1) s+=__shfl_xor_sync(0xffffffffu,s,o);
    if(lane==0) sred[w]=s;
    __syncthreads();
    s=sred[0]+sred[1]+sred[2]+sred[3];
    float r=1.f/s;
#pragma unroll
    for(int j=0;j<4;j++){ int c=tid+128*j; if(c<KKm) row[c]=v[j]*r; }
}

__global__ void k_resadd(const float* __restrict__ rc, const float* __restrict__ utt){
    size_t i=(size_t)blockIdx.x*blockDim.x+threadIdx.x;
    float4 o=((const float4*)g_out)[i];
    size_t rc4=(size_t)RRm*BD/4;
    float4 s=(i<rc4)?((const float4*)rc)[i]:((const float4*)utt)[i-rc4];
    ((float4*)g_res)[i]=make_float4(o.x+s.x,o.y+s.y,o.z+s.z,o.w+s.w);
}
__global__ void k_clip(float* __restrict__ dout){
    size_t i=(size_t)blockIdx.x*blockDim.x+threadIdx.x;
    float4 v=((const float4*)(g_out+(size_t)TTm*BD))[i];
    v.x=fminf(fmaxf(v.x,-10.f),10.f); v.y=fminf(fmaxf(v.y,-10.f),10.f);
    v.z=fminf(fmaxf(v.z,-10.f),10.f); v.w=fminf(fmaxf(v.w,-10.f),10.f);
    ((float4*)(dout+S2_OFF))[i]=v;
}

extern "C" void kernel_launch(void* const* d_in, const int* in_sizes, int n_in,
                              void* d_out_v, int out_size) {
    const float* utterance=(const float*)d_in[0];
    const float* right_ctx=(const float*)d_in[1];
    const float* mems_in=(const float*)d_in[2];
    const float* state_mems=(const float*)d_in[3];
    const float* lc_key=(const float*)d_in[4];
    const float* lc_val=(const float*)d_in[5];
    const float* W_kv=(const float*)d_in[6];
    const float* b_kv=(const float*)d_in[7];
    const float* W_q=(const float*)d_in[8];
    const float* b_q=(const float*)d_in[9];
    const float* W_out=(const float*)d_in[10];
    const float* b_out=(const float*)d_in[11];
    const float* ln_in_g=(const float*)d_in[12];
    const float* ln_in_b=(const float*)d_in[13];
    const float* ln_ff_g=(const float*)d_in[14];
    const float* ln_ff_b=(const float*)d_in[15];
    const float* W_ff1=(const float*)d_in[16];
    const float* b_ff1=(const float*)d_in[17];
    const float* W_ff2=(const float*)d_in[18];
    const float* b_ff2=(const float*)d_in[19];
    const float* ln_out_g=(const float*)d_in[20];
    const float* ln_out_b=(const float*)d_in[21];
    const int* past_len=(const int*)d_in[22];
    float* dout=(float*)d_out_v;

    float *q,*k,*v,*scores,*attn,*outb,*ff2b;
    bf16 *cath,*catl,*ffinh,*ffinl,*ffhh,*ffhl,*attnh,*attnl;
    bf16 *wqh,*wql,*wkvh,*wkvl,*woh,*wol,*w1h,*w1l,*w2h,*w2l;
    cudaGetSymbolAddress((void**)&q,g_q); cudaGetSymbolAddress((void**)&k,g_k);
    cudaGetSymbolAddress((void**)&v,g_v); cudaGetSymbolAddress((void**)&scores,g_scores);
    cudaGetSymbolAddress((void**)&attn,g_attn); cudaGetSymbolAddress((void**)&outb,g_out);
    cudaGetSymbolAddress((void**)&ff2b,g_ff2);
    cudaGetSymbolAddress((void**)&cath,g_cat_h); cudaGetSymbolAddress((void**)&catl,g_cat_l);
    cudaGetSymbolAddress((void**)&ffinh,g_ffin_h); cudaGetSymbolAddress((void**)&ffinl,g_ffin_l);
    cudaGetSymbolAddress((void**)&ffhh,g_ffh_h); cudaGetSymbolAddress((void**)&ffhl,g_ffh_l);
    cudaGetSymbolAddress((void**)&attnh,g_attn_h); cudaGetSymbolAddress((void**)&attnl,g_attn_l);
    cudaGetSymbolAddress((void**)&wqh,g_wq_h); cudaGetSymbolAddress((void**)&wql,g_wq_l);
    cudaGetSymbolAddress((void**)&wkvh,g_wkv_h); cudaGetSymbolAddress((void**)&wkvl,g_wkv_l);
    cudaGetSymbolAddress((void**)&woh,g_wo_h); cudaGetSymbolAddress((void**)&wol,g_wo_l);
    cudaGetSymbolAddress((void**)&w1h,g_w1_h); cudaGetSymbolAddress((void**)&w1l,g_w1_l);
    cudaGetSymbolAddress((void**)&w2h,g_w2_h); cudaGetSymbolAddress((void**)&w2l,g_w2_l);

    // splits
    k_split<<<(4*BD/4)/256,256>>>(state_mems, cath, catl);
    k_split<<<(Dm*Dm/4)/256,256>>>(W_q, wqh, wql);
    k_split<<<(2*Dm*Dm/4)/256,256>>>(W_kv, wkvh, wkvl);
    k_split<<<(Dm*Dm/4)/256,256>>>(W_out, woh, wol);
    k_split<<<((size_t)FFNm*Dm/4)/256,256>>>(W_ff1, w1h, w1l);
    k_split<<<((size_t)FFNm*Dm/4)/256,256>>>(W_ff2, w2h, w2l);
    // LN + summary
    k_ln_in<<<TTm*BBm,256>>>(right_ctx, utterance, ln_in_g, ln_in_b);
    k_summary<<<BD/256,256>>>();
    // projections (HMMA)
    gemm_mma<<<dim3(8,81),256>>>(cath+(size_t)4*BD, catl+(size_t)4*BD, Dm, wqh, wql, Dm,
        b_q, q, nullptr, nullptr, Dm, QQm*BBm, Dm, 0);
    gemm_mma<<<dim3(8,18),256>>>(cath, catl, Dm, wkvh, wkvl, Dm,
        b_kv, k, nullptr, nullptr, Dm, 36*BBm, Dm, 0);
    gemm_mma<<<dim3(8,64),256>>>(cath+(size_t)36*BD, catl+(size_t)36*BD, Dm, wkvh, wkvl, Dm,
        b_kv, k+(size_t)292*BD, nullptr, nullptr, Dm, UUm*BBm, Dm, 0);
    gemm_mma<<<dim3(8,18),256>>>(cath, catl, Dm, wkvh+(size_t)Dm*Dm, wkvl+(size_t)Dm*Dm, Dm,
        b_kv+Dm, v, nullptr, nullptr, Dm, 36*BBm, Dm, 0);
    gemm_mma<<<dim3(8,64),256>>>(cath+(size_t)36*BD, catl+(size_t)36*BD, Dm, wkvh+(size_t)Dm*Dm, wkvl+(size_t)Dm*Dm, Dm,
        b_kv+Dm, v+(size_t)292*BD, nullptr, nullptr, Dm, UUm*BBm, Dm, 0);
    cudaMemcpyAsync(k+(size_t)36*BD, lc_key, (size_t)LLm*BD*sizeof(float), cudaMemcpyDeviceToDevice, 0);
    cudaMemcpyAsync(v+(size_t)36*BD, lc_val, (size_t)LLm*BD*sizeof(float), cudaMemcpyDeviceToDevice, 0);
    // attention (SIMT fp32)
    gemm_nt<<<dim3(7,2,1024),256>>>(q, BD, 64, k, BD, 64, scores, KKm, (long)QQm*KKm, QQm, KKm, 64, 0.125f);
    k_softmax<<<1024*QQm,128>>>(past_len);
    gemm_nn<<<dim3(1,2,1024),256>>>(scores, KKm, (long)QQm*KKm, v, BD, 64, attn, BD, 64, QQm, 64, KKm);
    // out proj
    k_split<<<((size_t)QQm*BD/4)/256,256>>>(attn, attnh, attnl);
    gemm_mma<<<dim3(8,81),256>>>(attnh, attnl, Dm, woh, wol, Dm,
        b_out, outb, nullptr, nullptr, Dm, QQm*BBm, Dm, 0);
    k_resadd<<<(TTm*BD/4)/256,256>>>(right_ctx, utterance);
    k_clip<<<(BD/4)/256,256>>>(dout);
    // FFN
    k_ln_ff<<<TTm*BBm,256>>>(ln_ff_g, ln_ff_b);
    gemm_mma<<<dim3(32,80),256>>>(ffinh, ffinl, Dm, w1h, w1l, Dm,
        b_ff1, nullptr, ffhh, ffhl, FFNm, TTm*BBm, Dm, 1);
    gemm_mma<<<dim3(8,80),256>>>(ffhh, ffhl, FFNm, w2h, w2l, FFNm,
        b_ff2, ff2b, nullptr, nullptr, Dm, TTm*BBm, FFNm, 0);
    k_ln_final<<<TTm*BBm,256>>>(ln_out_g, ln_out_b, dout);
    // state-carry
    cudaMemcpyAsync(dout+S3_OFF, state_mems+BD, (size_t)3*BD*sizeof(float), cudaMemcpyDeviceToDevice, 0);
    cudaMemcpyAsync(dout+S3_OFF+(size_t)3*BD, mems_in, (size_t)BD*sizeof(float), cudaMemcpyDeviceToDevice, 0);
    cudaMemcpyAsync(dout+S4_OFF, lc_key+(size_t)128*BD, (size_t)128*BD*sizeof(float), cudaMemcpyDeviceToDevice, 0);
    cudaMemcpyAsync(dout+S4_OFF+(size_t)128*BD, k+(size_t)292*BD, (size_t)128*BD*sizeof(float), cudaMemcpyDeviceToDevice, 0);
    cudaMemcpyAsync(dout+S5_OFF, lc_val+(size_t)128*BD, (size_t)128*BD*sizeof(float), cudaMemcpyDeviceToDevice, 0);
    cudaMemcpyAsync(dout+S5_OFF+(size_t)128*BD, v+(size_t)292*BD, (size_t)128*BD*sizeof(float), cudaMemcpyDeviceToDevice, 0);
}